// round 11
// baseline (speedup 1.0000x reference)
#include <cuda_runtime.h>
#include <cuda_bf16.h>
#include <cstdint>

#define NBINS   2200
#define NCHAN   12
#define NBATCH  32
#define PLANE   65536            // 256*256
#define SPLIT   2                // grid = 768: single wave
#define THREADS 256
#define N4PLANE (PLANE / 4)      // 16384 float4 per plane
#define HALF4   (N4PLANE / SPLIT)

// out = hist_counts (init before reductions; out is poisoned by harness)
__global__ void init_out_kernel(const float4* __restrict__ hist_in,
                                float4* __restrict__ out) {
    int i = blockIdx.x * blockDim.x + threadIdx.x;
    if (i < (NCHAN * NBINS) / 4) out[i] = hist_in[i];
}

// Shared-memory path (SM-side ATOMS pipe).
__device__ __forceinline__ void bin_sh(float f, int* sh) {
    if (f >= -1200.0f && f <= 1000.0f) {
        int idx = __float2int_rd(f + 1200.0f);
        atomicAdd(&sh[min(idx, NBINS - 1)], 1);
    }
}

// Global path (L2-side atomic ALUs — a second, otherwise-idle resource).
// Exact: integer-valued f32 adds, totals << 2^24. out is hist-initialized
// before this kernel runs (stream order).
__device__ __forceinline__ void bin_gl(float f, float* __restrict__ g) {
    if (f >= -1200.0f && f <= 1000.0f) {
        int idx = __float2int_rd(f + 1200.0f);
        asm volatile("red.global.add.f32 [%0], %1;"
                     :: "l"(&g[min(idx, NBINS - 1)]), "f"(1.0f) : "memory");
    }
}

// 3 elements -> shared ATOMS, 1 element -> global RED (25% offload).
__device__ __forceinline__ void bin4(float4 v, int* sh, float* __restrict__ g) {
    bin_sh(v.x, sh);
    bin_sh(v.y, sh);
    bin_sh(v.z, sh);
    bin_gl(v.w, g);
}

__global__ __launch_bounds__(THREADS)
void hist_kernel(const float* __restrict__ x, float* __restrict__ out) {
    __shared__ int sh[NBINS];
    for (int i = threadIdx.x; i < NBINS; i += THREADS) sh[i] = 0;
    __syncthreads();

    const int plane = blockIdx.x >> 1;     // b * NCHAN + c  (B,C,H,W layout)
    const int part  = blockIdx.x & 1;
    const int chan  = plane % NCHAN;

    float* __restrict__ g = out + chan * NBINS;

    const float4* __restrict__ p = reinterpret_cast<const float4*>(x)
        + (size_t)plane * N4PLANE + (size_t)part * HALF4;

    // 8192 float4 / 256 threads = 32 per thread; 2 front-batched loads/iter.
    #pragma unroll
    for (int i = threadIdx.x; i < HALF4; i += 2 * THREADS) {
        float4 a = p[i];
        float4 b = p[i + THREADS];
        bin4(a, sh, g);
        bin4(b, sh, g);
    }
    __syncthreads();

    // Flush shared counts as exact float REDs into the output.
    for (int j = threadIdx.x; j < NBINS; j += THREADS) {
        int v = sh[j];
        if (v) {
            float fv = (float)v;
            asm volatile("red.global.add.f32 [%0], %1;"
                         :: "l"(&g[j]), "f"(fv) : "memory");
        }
    }
}

extern "C" void kernel_launch(void* const* d_in, const int* in_sizes, int n_in,
                              void* d_out, int out_size) {
    const float* x    = (const float*)d_in[0];       // [32,12,256,256] fp32
    const float* hist = (const float*)d_in[1];       // [12,2200] fp32
    float* out        = (float*)d_out;               // [12,2200] fp32

    const int n4 = (NCHAN * NBINS) / 4;              // 6600
    init_out_kernel<<<(n4 + 255) / 256, 256>>>((const float4*)hist, (float4*)out);
    hist_kernel<<<NBATCH * NCHAN * SPLIT, THREADS>>>(x, out);
}

// round 12
// speedup vs baseline: 3.5758x; 3.5758x over previous
#include <cuda_runtime.h>
#include <cuda_bf16.h>
#include <cstdint>

#define NBINS   2200
#define NCHAN   12
#define NBATCH  32
#define PLANE   65536            // 256*256
#define SPLIT   2                // grid = 768: single wave
#define THREADS 256
#define N4PLANE (PLANE / 4)      // 16384 float4 per plane
#define HALF4   (N4PLANE / SPLIT)
#define NCOPY   24               // prologue CTAs that copy hist_counts -> out
#define HIST4   ((NCHAN * NBINS) / 4)   // 6600 float4 of histogram state

// Self-resetting cross-block flags (last CTA resets; deterministic per replay).
__device__ int g_done = 0;
__device__ int g_fin  = 0;

__device__ __forceinline__ void bin1(float f, int* sh) {
    int idx = __float2int_rd(f + 1200.0f);
    // idx >= 0  <=>  f >= -1200 (floor monotone). f <= 1000 exact: values in
    // (1000, 1001) must be rejected; f == 1000 maps to the last bin via min.
    if (idx >= 0 && f <= 1000.0f) {
        atomicAdd(&sh[min(idx, NBINS - 1)], 1);
    }
}

__device__ __forceinline__ void bin4(float4 v, int* sh) {
    bin1(v.x, sh); bin1(v.y, sh); bin1(v.z, sh); bin1(v.w, sh);
}

__global__ __launch_bounds__(THREADS)
void hist_kernel(const float* __restrict__ x,
                 const float4* __restrict__ hist_in,
                 float* __restrict__ out) {
    __shared__ int sh[NBINS];

    // ---- Prologue: first NCOPY CTAs publish out = hist_counts ----
    if (blockIdx.x < NCOPY) {
        float4* __restrict__ o4 = reinterpret_cast<float4*>(out);
        const int per = HIST4 / NCOPY;        // 275
        const int base = blockIdx.x * per;
        for (int i = threadIdx.x; i < per; i += THREADS)
            o4[base + i] = hist_in[base + i];
        __threadfence();
        __syncthreads();                      // all copies done before signal
        if (threadIdx.x == 0) atomicAdd(&g_done, 1);
    }

    for (int i = threadIdx.x; i < NBINS; i += THREADS) sh[i] = 0;
    __syncthreads();

    const int plane = blockIdx.x >> 1;     // b * NCHAN + c  (B,C,H,W layout)
    const int part  = blockIdx.x & 1;
    const int chan  = plane % NCHAN;

    const float4* __restrict__ p = reinterpret_cast<const float4*>(x)
        + (size_t)plane * N4PLANE + (size_t)part * HALF4;

    // 8192 float4 / 256 threads = 32 per thread; 2 front-batched loads/iter.
    #pragma unroll
    for (int i = threadIdx.x; i < HALF4; i += 2 * THREADS) {
        float4 a = p[i];
        float4 b = p[i + THREADS];
        bin4(a, sh);
        bin4(b, sh);
    }
    __syncthreads();

    // ---- Gate: out must be initialized (satisfied long ago; no real wait,
    // and all CTAs are co-resident in one wave so no deadlock risk) ----
    if (threadIdx.x == 0) {
        while (atomicAdd(&g_done, 0) < NCOPY) { }
    }
    __syncthreads();

    // ---- Flush shared counts as exact coalesced float REDs into out ----
    float* __restrict__ g = out + chan * NBINS;
    for (int j = threadIdx.x; j < NBINS; j += THREADS) {
        int v = sh[j];
        if (v) {
            float fv = (float)v;
            asm volatile("red.global.add.f32 [%0], %1;"
                         :: "l"(&g[j]), "f"(fv) : "memory");
        }
    }

    // ---- Self-clean flags for the next graph replay ----
    __syncthreads();
    if (threadIdx.x == 0) {
        if (atomicAdd(&g_fin, 1) == (int)gridDim.x - 1) {
            atomicExch(&g_fin, 0);
            atomicExch(&g_done, 0);
        }
    }
}

extern "C" void kernel_launch(void* const* d_in, const int* in_sizes, int n_in,
                              void* d_out, int out_size) {
    const float* x    = (const float*)d_in[0];       // [32,12,256,256] fp32
    const float* hist = (const float*)d_in[1];       // [12,2200] fp32
    float* out        = (float*)d_out;               // [12,2200] fp32

    hist_kernel<<<NBATCH * NCHAN * SPLIT, THREADS>>>(
        x, (const float4*)hist, out);
}

// round 13
// speedup vs baseline: 3.5803x; 1.0013x over previous
#include <cuda_runtime.h>
#include <cuda_bf16.h>
#include <cstdint>

#define NBINS   2200
#define NCHAN   12
#define NBATCH  32
#define PLANE   65536            // 256*256
#define SPLIT   2                // grid = 768: all CTAs co-resident (one wave)
#define THREADS 256
#define N4PLANE (PLANE / 4)      // 16384 float4 per plane
#define HALF4   (N4PLANE / SPLIT)
#define NCOPY   24               // prologue CTAs that copy hist_counts -> out
#define HIST4   ((NCHAN * NBINS) / 4)   // 6600 float4 of histogram state

// Self-resetting cross-block flags (last CTA resets; deterministic per replay).
__device__ int g_done = 0;
__device__ int g_fin  = 0;

__device__ __forceinline__ void bin1(float f, int* sh) {
    int idx = __float2int_rd(f + 1200.0f);
    // idx >= 0  <=>  f >= -1200 (floor monotone). f <= 1000 exact: values in
    // (1000, 1001) must be rejected; f == 1000 maps to the last bin via min.
    if (idx >= 0 && f <= 1000.0f) {
        atomicAdd(&sh[min(idx, NBINS - 1)], 1);
    }
}

__device__ __forceinline__ void bin4(float4 v, int* sh) {
    bin1(v.x, sh); bin1(v.y, sh); bin1(v.z, sh); bin1(v.w, sh);
}

__global__ __launch_bounds__(THREADS)
void hist_kernel(const float* __restrict__ x,
                 const float4* __restrict__ hist_in,
                 float* __restrict__ out) {
    __shared__ int sh[NBINS];

    // ---- Prologue: first NCOPY CTAs publish out = hist_counts ----
    if (blockIdx.x < NCOPY) {
        float4* __restrict__ o4 = reinterpret_cast<float4*>(out);
        const int per = HIST4 / NCOPY;        // 275
        const int base = blockIdx.x * per;
        for (int i = threadIdx.x; i < per; i += THREADS)
            o4[base + i] = hist_in[base + i];
        __threadfence();                      // release: stores visible first
        __syncthreads();                      // all copies done before signal
        if (threadIdx.x == 0) atomicAdd(&g_done, 1);
    }

    for (int i = threadIdx.x; i < NBINS; i += THREADS) sh[i] = 0;
    __syncthreads();

    const int plane = blockIdx.x >> 1;     // b * NCHAN + c  (B,C,H,W layout)
    const int part  = blockIdx.x & 1;
    const int chan  = plane % NCHAN;

    const float4* __restrict__ p = reinterpret_cast<const float4*>(x)
        + (size_t)plane * N4PLANE + (size_t)part * HALF4;

    // 8192 float4 / 256 threads = 32 per thread; 2 front-batched loads/iter.
    #pragma unroll
    for (int i = threadIdx.x; i < HALF4; i += 2 * THREADS) {
        float4 a = p[i];
        float4 b = p[i + THREADS];
        bin4(a, sh);
        bin4(b, sh);
    }
    __syncthreads();

    // ---- Gate: out initialized (satisfied ~20us ago; plain volatile poll,
    // no L2-atomic contention; all 768 CTAs co-resident -> no deadlock) ----
    if (threadIdx.x == 0) {
        while (*(volatile int*)&g_done < NCOPY) { }
    }
    __syncthreads();

    // ---- Flush shared counts as exact coalesced float REDs into out ----
    float* __restrict__ g = out + chan * NBINS;
    for (int j = threadIdx.x; j < NBINS; j += THREADS) {
        int v = sh[j];
        if (v) {
            float fv = (float)v;
            asm volatile("red.global.add.f32 [%0], %1;"
                         :: "l"(&g[j]), "f"(fv) : "memory");
        }
    }

    // ---- Self-clean flags for the next graph replay ----
    __syncthreads();
    if (threadIdx.x == 0) {
        if (atomicAdd(&g_fin, 1) == (int)gridDim.x - 1) {
            atomicExch(&g_fin, 0);
            atomicExch(&g_done, 0);
        }
    }
}

extern "C" void kernel_launch(void* const* d_in, const int* in_sizes, int n_in,
                              void* d_out, int out_size) {
    const float* x    = (const float*)d_in[0];       // [32,12,256,256] fp32
    const float* hist = (const float*)d_in[1];       // [12,2200] fp32
    float* out        = (float*)d_out;               // [12,2200] fp32

    hist_kernel<<<NBATCH * NCHAN * SPLIT, THREADS>>>(
        x, (const float4*)hist, out);
}

// round 14
// speedup vs baseline: 3.8478x; 1.0747x over previous
#include <cuda_runtime.h>
#include <cuda_bf16.h>

#define NBINS   2200
#define NCHAN   12
#define NBATCH  32
#define PLANE   65536            // 256*256
#define SPLIT   2                // blocks per (batch, channel) plane
#define THREADS 256
#define ELEMS_PER_BLOCK (PLANE / SPLIT)   // 32768 floats per block
#define N4      (ELEMS_PER_BLOCK / 4)     // 8192 float4 per block

// out = hist_counts (init before atomics; out is poisoned by harness)
__global__ void init_out_kernel(const float4* __restrict__ hist_in,
                                float4* __restrict__ out) {
    int i = blockIdx.x * blockDim.x + threadIdx.x;
    if (i < (NCHAN * NBINS) / 4) out[i] = hist_in[i];
}

__device__ __forceinline__ void bin1(float f, int* sh) {
    if (f >= -1200.0f && f <= 1000.0f) {
        int idx = __float2int_rd(f + 1200.0f);
        atomicAdd(&sh[min(idx, NBINS - 1)], 1);
    }
}

__global__ __launch_bounds__(THREADS)
void hist_kernel(const float* __restrict__ x, float* __restrict__ out) {
    __shared__ int sh[NBINS];
    for (int i = threadIdx.x; i < NBINS; i += THREADS) sh[i] = 0;
    __syncthreads();

    const int block = blockIdx.x;          // 0 .. NBATCH*NCHAN*SPLIT-1
    const int plane = block / SPLIT;       // b * NCHAN + c  (B,C,H,W layout)
    const int part  = block % SPLIT;
    const int chan  = plane % NCHAN;

    const float4* __restrict__ p = reinterpret_cast<const float4*>(
        x + (size_t)plane * PLANE + (size_t)part * ELEMS_PER_BLOCK);

    // 8192 float4 / 256 threads = 32 per thread; process 2 per iteration,
    // front-batched loads for MLP.
    #pragma unroll 4
    for (int i = threadIdx.x; i < N4; i += 2 * THREADS) {
        float4 a = p[i];
        float4 b = p[i + THREADS];
        bin1(a.x, sh); bin1(a.y, sh); bin1(a.z, sh); bin1(a.w, sh);
        bin1(b.x, sh); bin1(b.y, sh); bin1(b.z, sh); bin1(b.w, sh);
    }
    __syncthreads();

    // Flush shared counts as exact float REDs directly into the output.
    float* __restrict__ g = out + chan * NBINS;
    for (int i = threadIdx.x; i < NBINS; i += THREADS) {
        int v = sh[i];
        if (v) atomicAdd(&g[i], (float)v);
    }
}

extern "C" void kernel_launch(void* const* d_in, const int* in_sizes, int n_in,
                              void* d_out, int out_size) {
    const float* x    = (const float*)d_in[0];       // [32,12,256,256] fp32
    const float* hist = (const float*)d_in[1];       // [12,2200] fp32
    float* out        = (float*)d_out;               // [12,2200] fp32

    const int n4 = (NCHAN * NBINS) / 4;              // 6600
    init_out_kernel<<<(n4 + 255) / 256, 256>>>((const float4*)hist, (float4*)out);
    hist_kernel<<<NBATCH * NCHAN * SPLIT, THREADS>>>(x, out);
}